// round 11
// baseline (speedup 1.0000x reference)
#include <cuda_runtime.h>

#define NN 50000
#define NE 10000
#define D  128
#define NNZ_INC 400000
#define NNZ_E   80000
#define NNZ_V   400000
#define FULL 0xffffffffu

// ---------------- scratch (device globals; no allocation allowed) ----------------
__device__ __align__(128) float g_Tv[NE * D];
__device__ __align__(128) float g_Q[NE * D];
__device__ __align__(128) float g_Q2[NE * D];
__device__ __align__(128) float g_S1[NE];
__device__ __align__(128) float g_cnt[NE];
__device__ __align__(128) float g_A[NE * D];
__device__ __align__(128) float g_ef1[NE * D];
__device__ __align__(128) float g_T2[NE * D];
__device__ __align__(128) float g_ef2[NE * D];
__device__ __align__(128) float g_M[NE * D];
__device__ __align__(128) float g_vf[NN * D];
__device__ __align__(128) float g_vf2[NN * D];
__device__ __align__(128) float g_vf2m[NN * D];

// ---------------- CSR structures (built on device each launch) ----------------
__device__ int g_eCnt[NE], g_ePtr[NE + 1], g_eCur[NE];
__device__ int g_vCnt[NN], g_vPtr[NN + 1], g_vCur[NN];
__device__ int g_emCnt[NE], g_emPtr[NE + 1], g_emCur[NE];
__device__ int g_vmCnt[NN], g_vmPtr[NN + 1], g_vmCur[NN];
__device__ int   g_eIdx[NNZ_INC];
__device__ int   g_vIdx[NNZ_INC];
__device__ int   g_emCol[NNZ_E];
__device__ float g_emVal[NNZ_E];
__device__ int   g_vmCol[NNZ_V];
__device__ float g_vmVal[NNZ_V];

// ---------------- build step 1: zero counters ----------------
__global__ void zero_counters() {
    int t = blockIdx.x * 256 + threadIdx.x;
    if (t < NE) { g_eCnt[t] = 0; g_emCnt[t] = 0; }
    if (t < NN) { g_vCnt[t] = 0; g_vmCnt[t] = 0; }
}

// ---------------- build step 2: fused histograms ----------------
__global__ void hist_kernel(const int* __restrict__ src, const int* __restrict__ dst,
                            const int* __restrict__ em_r, const int* __restrict__ vm_r) {
    int i = blockIdx.x * 256 + threadIdx.x;
    if (i < NNZ_INC) {
        atomicAdd(g_eCnt + dst[i], 1);
        atomicAdd(g_vCnt + src[i], 1);
        atomicAdd(g_vmCnt + vm_r[i], 1);
    }
    if (i < NNZ_E) atomicAdd(g_emCnt + em_r[i], 1);
}

// ---------------- build step 3: exclusive scan (one block per array) ----------------
__device__ void scan_impl(const int* __restrict__ cnt, int* __restrict__ ptr,
                          int* __restrict__ cur, int n) {
    __shared__ int part[1024];
    int t = threadIdx.x;
    int chunk = (n + 1023) >> 10;
    int lo = t * chunk, hi = min(lo + chunk, n);
    int s = 0;
    for (int i = lo; i < hi; i++) s += cnt[i];
    part[t] = s;
    __syncthreads();
    for (int off = 1; off < 1024; off <<= 1) {
        int mine = part[t];
        int add = (t >= off) ? part[t - off] : 0;
        __syncthreads();
        part[t] = mine + add;
        __syncthreads();
    }
    int run = (t > 0) ? part[t - 1] : 0;
    for (int i = lo; i < hi; i++) { ptr[i] = run; cur[i] = run; run += cnt[i]; }
    if (t == 1023) ptr[n] = part[1023];
}

__global__ void scan_kernel() {
    switch (blockIdx.x) {
        case 0: scan_impl(g_eCnt,  g_ePtr,  g_eCur,  NE); break;
        case 1: scan_impl(g_vCnt,  g_vPtr,  g_vCur,  NN); break;
        case 2: scan_impl(g_emCnt, g_emPtr, g_emCur, NE); break;
        case 3: scan_impl(g_vmCnt, g_vmPtr, g_vmCur, NN); break;
    }
}

// ---------------- build step 4: fused binning ----------------
__global__ void bin_kernel(const int* __restrict__ src, const int* __restrict__ dst,
                           const int* __restrict__ em_r, const int* __restrict__ em_c,
                           const float* __restrict__ em_v,
                           const int* __restrict__ vm_r, const int* __restrict__ vm_c,
                           const float* __restrict__ vm_v) {
    int i = blockIdx.x * 256 + threadIdx.x;
    if (i < NNZ_INC) {
        int s = src[i], e = dst[i];
        int p0 = atomicAdd(g_eCur + e, 1);
        g_eIdx[p0] = s;
        int p1 = atomicAdd(g_vCur + s, 1);
        g_vIdx[p1] = e;
        int p3 = atomicAdd(g_vmCur + vm_r[i], 1);
        g_vmCol[p3] = vm_c[i];
        g_vmVal[p3] = vm_v[i];
    }
    if (i < NNZ_E) {
        int p2 = atomicAdd(g_emCur + em_r[i], 1);
        g_emCol[p2] = em_c[i];
        g_emVal[p2] = em_v[i];
    }
}

// =============== gather kernels: shfl-broadcast pattern ======================
// One coalesced index load per 32 entries, then shfl the index to all lanes so
// the feature loads are register-dependent only (independent memory ops that
// pipeline with MLP ~ unroll depth, instead of idx->feature dependent chains).

// ---- Tv[e] = sum invDV[s]*vfeat[s]; S1[e]; cnt[e] ----
__global__ void edge_pass1(const float* __restrict__ vfeat, const float* __restrict__ invDV) {
    int e = (blockIdx.x * blockDim.x + threadIdx.x) >> 5;
    if (e >= NE) return;
    int lane = threadIdx.x & 31;
    int b = g_ePtr[e], t = g_ePtr[e + 1];
    float4 acc = make_float4(0.f, 0.f, 0.f, 0.f);
    float wsum = 0.f;
    for (int base = b; base < t; base += 32) {
        int k = base + lane;
        int idx = (k < t) ? g_eIdx[k] : 0;
        float w = (k < t) ? __ldg(invDV + idx) : 0.f;
        wsum += w;
        int n = min(32, t - base);
#pragma unroll 4
        for (int j = 0; j < n; j++) {
            int s = __shfl_sync(FULL, idx, j);
            float wj = __shfl_sync(FULL, w, j);
            float4 v = __ldg(reinterpret_cast<const float4*>(vfeat + (size_t)s * D) + lane);
            acc.x += wj * v.x; acc.y += wj * v.y; acc.z += wj * v.z; acc.w += wj * v.w;
        }
    }
#pragma unroll
    for (int o = 16; o; o >>= 1) wsum += __shfl_xor_sync(FULL, wsum, o);
    reinterpret_cast<float4*>(g_Tv + (size_t)e * D)[lane] = acc;
    if (lane == 0) { g_S1[e] = wsum; g_cnt[e] = (float)(t - b); }
}

// ---- Y[node] = sum X[edge] over node's incidences ----
__device__ __forceinline__ void node_gather_body(const float* __restrict__ X,
                                                 float* __restrict__ Y) {
    int s = (blockIdx.x * blockDim.x + threadIdx.x) >> 5;
    if (s >= NN) return;
    int lane = threadIdx.x & 31;
    int b = g_vPtr[s], t = g_vPtr[s + 1];
    float4 acc = make_float4(0.f, 0.f, 0.f, 0.f);
    for (int base = b; base < t; base += 32) {
        int k = base + lane;
        int idx = (k < t) ? g_vIdx[k] : 0;
        int n = min(32, t - base);
#pragma unroll 4
        for (int j = 0; j < n; j++) {
            int e = __shfl_sync(FULL, idx, j);
            float4 v = __ldg(reinterpret_cast<const float4*>(X + (size_t)e * D) + lane);
            acc.x += v.x; acc.y += v.y; acc.z += v.z; acc.w += v.w;
        }
    }
    reinterpret_cast<float4*>(Y + (size_t)s * D)[lane] = acc;
}

// __device__ globals MUST be bound from device code (host shadow-address trap — R8 bug)
__global__ void node_gather_vf2(const float* __restrict__ efeat) {
    node_gather_body(efeat, g_vf2);
}
__global__ void node_gather_vf() {
    node_gather_body(g_ef1, g_vf);
}

// ---- T2[e]=sum vout[s]; ef2[e]=sum vf2m[s] (shared index set) ----
__global__ void edge_pass3(const float* __restrict__ vout) {
    int e = (blockIdx.x * blockDim.x + threadIdx.x) >> 5;
    if (e >= NE) return;
    int lane = threadIdx.x & 31;
    int b = g_ePtr[e], t = g_ePtr[e + 1];
    float4 a1 = make_float4(0.f, 0.f, 0.f, 0.f);
    float4 a2 = make_float4(0.f, 0.f, 0.f, 0.f);
    for (int base = b; base < t; base += 32) {
        int k = base + lane;
        int idx = (k < t) ? g_eIdx[k] : 0;
        int n = min(32, t - base);
#pragma unroll 4
        for (int j = 0; j < n; j++) {
            int s = __shfl_sync(FULL, idx, j);
            float4 u = __ldg(reinterpret_cast<const float4*>(vout + (size_t)s * D) + lane);
            float4 w = __ldg(reinterpret_cast<const float4*>(g_vf2m + (size_t)s * D) + lane);
            a1.x += u.x; a1.y += u.y; a1.z += u.z; a1.w += u.w;
            a2.x += w.x; a2.y += w.y; a2.z += w.z; a2.w += w.w;
        }
    }
    reinterpret_cast<float4*>(g_T2 + (size_t)e * D)[lane] = a1;
    reinterpret_cast<float4*>(g_ef2 + (size_t)e * D)[lane] = a2;
}

// ---- CSR SpMM gather: Y[r] = seed(r) + sum val*X[col] ----
template <bool SEED>
__device__ __forceinline__ void spmm_gather_body(const int* __restrict__ ptr,
                                                 const int* __restrict__ col,
                                                 const float* __restrict__ val,
                                                 const float* __restrict__ X,
                                                 const float* __restrict__ seed,
                                                 float* __restrict__ Y, int nrows) {
    int r = (blockIdx.x * blockDim.x + threadIdx.x) >> 5;
    if (r >= nrows) return;
    int lane = threadIdx.x & 31;
    int b = ptr[r], t = ptr[r + 1];
    float4 acc;
    if (SEED) acc = __ldg(reinterpret_cast<const float4*>(seed + (size_t)r * D) + lane);
    else      acc = make_float4(0.f, 0.f, 0.f, 0.f);
    for (int base = b; base < t; base += 32) {
        int k = base + lane;
        int idx = (k < t) ? col[k] : 0;
        float v  = (k < t) ? val[k] : 0.f;
        int n = min(32, t - base);
#pragma unroll 4
        for (int j = 0; j < n; j++) {
            int c = __shfl_sync(FULL, idx, j);
            float vj = __shfl_sync(FULL, v, j);
            float4 x = __ldg(reinterpret_cast<const float4*>(X + (size_t)c * D) + lane);
            acc.x += vj * x.x; acc.y += vj * x.y; acc.z += vj * x.z; acc.w += vj * x.w;
        }
    }
    reinterpret_cast<float4*>(Y + (size_t)r * D)[lane] = acc;
}

__global__ void spmm_e_gather(const float* __restrict__ efeat) {
    spmm_gather_body<true>(g_emPtr, g_emCol, g_emVal, g_A, efeat, g_ef1, NE);
}
__global__ void spmm_v_gather() {
    spmm_gather_body<false>(g_vmPtr, g_vmCol, g_vmVal, g_vf2, nullptr, g_vf2m, NN);
}

// ---------------- GEMM: Y = X[rows,128] @ W.T (+ epilogue) ----------------
// MODE 0: plain   MODE 1: Y=acc+(P1+bias)*sc1   MODE 2: relu
// MODE 3: Y = addm + sc2*(acc + sc1*(P1+bias))
// ws row stride must be a multiple of 4 floats (LDS.128 alignment).
template <int MODE>
__device__ __forceinline__ void gemm_body(const float* __restrict__ X, const float* __restrict__ W,
                                          int ldw, int koff, float* __restrict__ Y, int rows,
                                          const float* __restrict__ P1, const float* __restrict__ sc1,
                                          const float* __restrict__ sc2, const float* __restrict__ bias,
                                          const float* __restrict__ addm) {
    __shared__ float xs[32][128];
    __shared__ __align__(16) float ws[32][132];
    int r0 = blockIdx.x * 32;
    int tid = threadIdx.x;

    for (int idx = tid; idx < 32 * 128; idx += 256) {
        int r = idx >> 7, k = idx & 127;
        int rr = r0 + r;
        xs[r][k] = (rr < rows) ? X[(size_t)rr * 128 + k] : 0.f;
    }

    int lane = tid & 31;
    int rloc = (tid >> 5) * 4;
    int o4 = lane * 4;
    float acc[4][4];
#pragma unroll
    for (int i = 0; i < 4; i++)
#pragma unroll
        for (int j = 0; j < 4; j++) acc[i][j] = 0.f;

    for (int kt = 0; kt < 128; kt += 32) {
        __syncthreads();
        for (int idx = tid; idx < 32 * 128; idx += 256) {
            int o = idx >> 5, kk = idx & 31;
            ws[kk][o] = W[(size_t)o * ldw + koff + kt + kk];
        }
        __syncthreads();
#pragma unroll
        for (int kk = 0; kk < 32; kk++) {
            float4 wv = *reinterpret_cast<const float4*>(&ws[kk][o4]);
#pragma unroll
            for (int i = 0; i < 4; i++) {
                float xv = xs[rloc + i][kt + kk];
                acc[i][0] += xv * wv.x;
                acc[i][1] += xv * wv.y;
                acc[i][2] += xv * wv.z;
                acc[i][3] += xv * wv.w;
            }
        }
    }

#pragma unroll
    for (int i = 0; i < 4; i++) {
        int rr = r0 + rloc + i;
        if (rr >= rows) continue;
        float4 res = make_float4(acc[i][0], acc[i][1], acc[i][2], acc[i][3]);
        if (MODE == 1) {
            float s = sc1[rr];
            float4 q = *reinterpret_cast<const float4*>(P1 + (size_t)rr * 128 + o4);
            float4 b = *reinterpret_cast<const float4*>(bias + o4);
            res.x += (q.x + b.x) * s;
            res.y += (q.y + b.y) * s;
            res.z += (q.z + b.z) * s;
            res.w += (q.w + b.w) * s;
        } else if (MODE == 2) {
            res.x = fmaxf(res.x, 0.f); res.y = fmaxf(res.y, 0.f);
            res.z = fmaxf(res.z, 0.f); res.w = fmaxf(res.w, 0.f);
        } else if (MODE == 3) {
            float c = sc1[rr];
            float id = sc2[rr];
            float4 q = *reinterpret_cast<const float4*>(P1 + (size_t)rr * 128 + o4);
            float4 b = *reinterpret_cast<const float4*>(bias + o4);
            float4 a = *reinterpret_cast<const float4*>(addm + (size_t)rr * 128 + o4);
            res.x = a.x + id * (res.x + c * (q.x + b.x));
            res.y = a.y + id * (res.y + c * (q.y + b.y));
            res.z = a.z + id * (res.z + c * (q.z + b.z));
            res.w = a.w + id * (res.w + c * (q.w + b.w));
        }
        *reinterpret_cast<float4*>(Y + (size_t)rr * 128 + o4) = res;
    }
}

// ---- fused Q/Q2 GEMM: shares the xs tile across both weight matrices ----
__global__ void gemm_QQ2_kernel(const float* __restrict__ efeat,
                                const float* __restrict__ p1W,
                                const float* __restrict__ p2W) {
    __shared__ float xs[32][128];
    __shared__ __align__(16) float ws[32][132];
    int r0 = blockIdx.x * 32;
    int tid = threadIdx.x;

    for (int idx = tid; idx < 32 * 128; idx += 256) {
        int r = idx >> 7, k = idx & 127;
        int rr = r0 + r;
        xs[r][k] = (rr < NE) ? efeat[(size_t)rr * 128 + k] : 0.f;
    }

    int lane = tid & 31;
    int rloc = (tid >> 5) * 4;
    int o4 = lane * 4;

#pragma unroll
    for (int w = 0; w < 2; w++) {
        const float* W = w ? p2W : p1W;
        float* Y = w ? g_Q2 : g_Q;
        float acc[4][4];
#pragma unroll
        for (int i = 0; i < 4; i++)
#pragma unroll
            for (int j = 0; j < 4; j++) acc[i][j] = 0.f;

        for (int kt = 0; kt < 128; kt += 32) {
            __syncthreads();
            for (int idx = tid; idx < 32 * 128; idx += 256) {
                int o = idx >> 5, kk = idx & 31;
                ws[kk][o] = W[(size_t)o * 256 + 128 + kt + kk];
            }
            __syncthreads();
#pragma unroll
            for (int kk = 0; kk < 32; kk++) {
                float4 wv = *reinterpret_cast<const float4*>(&ws[kk][o4]);
#pragma unroll
                for (int i = 0; i < 4; i++) {
                    float xv = xs[rloc + i][kt + kk];
                    acc[i][0] += xv * wv.x;
                    acc[i][1] += xv * wv.y;
                    acc[i][2] += xv * wv.z;
                    acc[i][3] += xv * wv.w;
                }
            }
        }
#pragma unroll
        for (int i = 0; i < 4; i++) {
            int rr = r0 + rloc + i;
            if (rr < NE)
                *reinterpret_cast<float4*>(Y + (size_t)rr * 128 + o4) =
                    make_float4(acc[i][0], acc[i][1], acc[i][2], acc[i][3]);
        }
    }
}

__global__ void gemm_A_kernel(const float* p1W, const float* p1b) {
    gemm_body<1>(g_Tv, p1W, 256, 0, g_A, NE, g_Q, g_S1, nullptr, p1b, nullptr);
}
__global__ void gemm_vout_kernel(const float* Wv, float* vout) {
    gemm_body<2>(g_vf, Wv, 128, 0, vout, NN, nullptr, nullptr, nullptr, nullptr, nullptr);
}
__global__ void gemm_B_kernel(const float* p2W, const float* p2b, const float* invDE) {
    gemm_body<3>(g_T2, p2W, 256, 0, g_M, NE, g_Q2, g_cnt, invDE, p2b, g_ef2);
}
__global__ void gemm_eout_kernel(const float* We, float* eout) {
    gemm_body<2>(g_M, We, 128, 0, eout, NE, nullptr, nullptr, nullptr, nullptr, nullptr);
}

// ---------------- launcher (two-stream fork/join, graph-capturable) ----------------
extern "C" void kernel_launch(void* const* d_in, const int* in_sizes, int n_in,
                              void* d_out, int out_size) {
    const float* vfeat  = (const float*)d_in[0];
    const float* efeat  = (const float*)d_in[1];
    const float* invDV  = (const float*)d_in[2];
    const float* invDE  = (const float*)d_in[3];
    const int*   inc_src = (const int*)d_in[4];
    const int*   inc_dst = (const int*)d_in[5];
    const int*   em_r   = (const int*)d_in[6];
    const int*   em_c   = (const int*)d_in[7];
    const float* em_v   = (const float*)d_in[8];
    const int*   vm_r   = (const int*)d_in[9];
    const int*   vm_c   = (const int*)d_in[10];
    const float* vm_v   = (const float*)d_in[11];
    const float* Wv     = (const float*)d_in[12];
    const float* We     = (const float*)d_in[13];
    const float* p1W    = (const float*)d_in[14];
    const float* p1b    = (const float*)d_in[15];
    const float* p2W    = (const float*)d_in[16];
    const float* p2b    = (const float*)d_in[17];

    float* out  = (float*)d_out;
    float* vout = out;                       // [NN, 128]
    float* eout = out + (size_t)NN * D;      // [NE, 128]

    static cudaStream_t s1 = nullptr;
    static cudaEvent_t evFork = nullptr, evBuild = nullptr, ev1 = nullptr, ev2 = nullptr;
    if (s1 == nullptr) {
        cudaStreamCreateWithFlags(&s1, cudaStreamNonBlocking);
        cudaEventCreateWithFlags(&evFork, cudaEventDisableTiming);
        cudaEventCreateWithFlags(&evBuild, cudaEventDisableTiming);
        cudaEventCreateWithFlags(&ev1, cudaEventDisableTiming);
        cudaEventCreateWithFlags(&ev2, cudaEventDisableTiming);
    }

    const int TB = 256;
    int grid_z    = (NN + TB - 1) / TB;
    int grid_nnz  = (NNZ_INC + TB - 1) / TB;
    int grid_eW   = (NE * 32 + TB - 1) / TB;         // warp per edge
    int grid_nW   = (NN * 32 + TB - 1) / TB;         // warp per node
    int grid_gE   = (NE + 31) / 32;
    int grid_gN   = (NN + 31) / 32;

    // fork immediately: s1 runs gemm_QQ2 concurrent with the CSR build
    cudaEventRecord(evFork, 0);
    cudaStreamWaitEvent(s1, evFork, 0);
    gemm_QQ2_kernel<<<grid_gE, TB, 0, s1>>>(efeat, p1W, p2W);  // Q, Q2 (hidden under build)

    // --- CSR build (stream 0) ---
    zero_counters<<<grid_z, TB>>>();
    hist_kernel<<<grid_nnz, TB>>>(inc_src, inc_dst, em_r, vm_r);
    scan_kernel<<<4, 1024>>>();
    bin_kernel<<<grid_nnz, TB>>>(inc_src, inc_dst, em_r, em_c, em_v, vm_r, vm_c, vm_v);
    cudaEventRecord(evBuild, 0);

    // --- s1: gather-only branch (needs build) ---
    cudaStreamWaitEvent(s1, evBuild, 0);
    edge_pass1<<<grid_eW, TB, 0, s1>>>(vfeat, invDV);          // Tv, S1, cnt
    cudaEventRecord(ev1, s1);
    node_gather_vf2<<<grid_nW, TB, 0, s1>>>(efeat);            // vf2
    spmm_v_gather<<<grid_nW, TB, 0, s1>>>();                   // vf2m = vmat@vf2
    cudaEventRecord(ev2, s1);

    // --- main stream: compute chain ---
    cudaStreamWaitEvent(0, ev1, 0);                            // need Tv/S1 (and Q via s1 order)
    gemm_A_kernel<<<grid_gE, TB>>>(p1W, p1b);                  // A
    spmm_e_gather<<<grid_eW, TB>>>(efeat);                     // ef1 = efeat + emat@A
    node_gather_vf<<<grid_nW, TB>>>();                         // vf
    gemm_vout_kernel<<<grid_gN, TB>>>(Wv, vout);               // vout = relu(vf@Wv.T)
    cudaStreamWaitEvent(0, ev2, 0);                            // join s1 (vf2m)
    edge_pass3<<<grid_eW, TB>>>(vout);                         // T2, ef2
    gemm_B_kernel<<<grid_gE, TB>>>(p2W, p2b, invDE);           // M
    gemm_eout_kernel<<<grid_gE, TB>>>(We, eout);               // eout
}

// round 16
// speedup vs baseline: 1.4221x; 1.4221x over previous
#include <cuda_runtime.h>

#define NN 50000
#define NE 10000
#define D  128
#define NNZ_INC 400000
#define NNZ_E   80000
#define NNZ_V   400000
#define FULL 0xffffffffu

// scan block decomposition: 256 elems/block
#define B_E 40            // ceil(NE/256)
#define B_N 196           // ceil(NN/256)
#define NBLK (B_E + B_N + B_E + B_N)   // 472
// segment starts in block space: [0,40) e, [40,236) v, [236,276) em, [276,472) vm

// ---------------- scratch (device globals; no allocation allowed) ----------------
__device__ __align__(128) float g_Tv[NE * D];
__device__ __align__(128) float g_Q[NE * D];
__device__ __align__(128) float g_Q2[NE * D];
__device__ __align__(128) float g_S1[NE];
__device__ __align__(128) float g_cnt[NE];
__device__ __align__(128) float g_A[NE * D];
__device__ __align__(128) float g_ef1[NE * D];
__device__ __align__(128) float g_T2[NE * D];
__device__ __align__(128) float g_ef2[NE * D];
__device__ __align__(128) float g_M[NE * D];
__device__ __align__(128) float g_vf[NN * D];
__device__ __align__(128) float g_vf2[NN * D];
__device__ __align__(128) float g_vf2m[NN * D];

// ---------------- CSR structures ----------------
__device__ int g_eCnt[NE], g_ePtr[NE + 1], g_eCur[NE];
__device__ int g_vCnt[NN], g_vPtr[NN + 1], g_vCur[NN];
__device__ int g_emCnt[NE], g_emPtr[NE + 1], g_emCur[NE];
__device__ int g_vmCnt[NN], g_vmPtr[NN + 1], g_vmCur[NN];
__device__ int   g_eIdx[NNZ_INC];
__device__ int   g_vIdx[NNZ_INC];
__device__ int   g_emCol[NNZ_E];
__device__ float g_emVal[NNZ_E];
__device__ int   g_vmCol[NNZ_V];
__device__ float g_vmVal[NNZ_V];
__device__ int   g_blkSum[NBLK];
__device__ int   g_blkOff[NBLK];

// ---------------- build step 1: zero counters ----------------
__global__ void zero_counters() {
    int t = blockIdx.x * 256 + threadIdx.x;
    if (t < NE) { g_eCnt[t] = 0; g_emCnt[t] = 0; }
    if (t < NN) { g_vCnt[t] = 0; g_vmCnt[t] = 0; }
}

// ---------------- build step 2: fused histograms ----------------
__global__ void hist_kernel(const int* __restrict__ src, const int* __restrict__ dst,
                            const int* __restrict__ em_r, const int* __restrict__ vm_r) {
    int i = blockIdx.x * 256 + threadIdx.x;
    if (i < NNZ_INC) {
        atomicAdd(g_eCnt + dst[i], 1);
        atomicAdd(g_vCnt + src[i], 1);
        atomicAdd(g_vmCnt + vm_r[i], 1);
    }
    if (i < NNZ_E) atomicAdd(g_emCnt + em_r[i], 1);
}

// ---------------- 3-phase parallel scan over the 4 count arrays ----------------
__device__ __forceinline__ void scan_map(int bid, const int*& cnt, int*& ptr,
                                         int*& cur, int& n, int& b0) {
    if (bid < B_E)              { cnt = g_eCnt;  ptr = g_ePtr;  cur = g_eCur;  n = NE; b0 = 0; }
    else if (bid < B_E + B_N)   { cnt = g_vCnt;  ptr = g_vPtr;  cur = g_vCur;  n = NN; b0 = B_E; }
    else if (bid < 2*B_E + B_N) { cnt = g_emCnt; ptr = g_emPtr; cur = g_emCur; n = NE; b0 = B_E + B_N; }
    else                        { cnt = g_vmCnt; ptr = g_vmPtr; cur = g_vmCur; n = NN; b0 = 2*B_E + B_N; }
}

__global__ void scan_partial() {
    int bid = blockIdx.x, tid = threadIdx.x;
    const int* cnt; int *ptr, *cur; int n, b0;
    scan_map(bid, cnt, ptr, cur, n, b0);
    int i = (bid - b0) * 256 + tid;
    int x = (i < n) ? cnt[i] : 0;
#pragma unroll
    for (int o = 16; o; o >>= 1) x += __shfl_xor_sync(FULL, x, o);
    __shared__ int ws[8];
    if ((tid & 31) == 0) ws[tid >> 5] = x;
    __syncthreads();
    if (tid == 0) {
        int s = 0;
#pragma unroll
        for (int w = 0; w < 8; w++) s += ws[w];
        g_blkSum[bid] = s;
    }
}

__global__ void scan_offsets() {
    __shared__ int sums[NBLK];
    int tid = threadIdx.x;
    for (int i = tid; i < NBLK; i += 512) sums[i] = g_blkSum[i];
    __syncthreads();
    if (tid < 4) {
        const int lo[5] = {0, B_E, B_E + B_N, 2*B_E + B_N, NBLK};
        int run = 0;
        for (int i = lo[tid]; i < lo[tid + 1]; i++) { int v = sums[i]; sums[i] = run; run += v; }
    }
    __syncthreads();
    for (int i = tid; i < NBLK; i += 512) g_blkOff[i] = sums[i];
}

__global__ void scan_final() {
    int bid = blockIdx.x, tid = threadIdx.x;
    const int* cnt; int *ptr, *cur; int n, b0;
    scan_map(bid, cnt, ptr, cur, n, b0);
    int i = (bid - b0) * 256 + tid;
    int x = (i < n) ? cnt[i] : 0;
    int lane = tid & 31, w = tid >> 5;
    int v = x;
#pragma unroll
    for (int o = 1; o < 32; o <<= 1) {
        int y = __shfl_up_sync(FULL, v, o);
        if (lane >= o) v += y;
    }
    __shared__ int ws[8], wexc[8];
    if (lane == 31) ws[w] = v;
    __syncthreads();
    if (tid == 0) {
        int run = 0;
#pragma unroll
        for (int k = 0; k < 8; k++) { wexc[k] = run; run += ws[k]; }
    }
    __syncthreads();
    if (i < n) {
        int excl = g_blkOff[bid] + wexc[w] + v - x;
        ptr[i] = excl;
        cur[i] = excl;
    }
    if (bid == 0 && tid == 0) {
        g_ePtr[NE]  = NNZ_INC;   // array totals are compile-time constants
        g_vPtr[NN]  = NNZ_INC;
        g_emPtr[NE] = NNZ_E;
        g_vmPtr[NN] = NNZ_V;
    }
}

// ---------------- build step 4: fused binning ----------------
__global__ void bin_kernel(const int* __restrict__ src, const int* __restrict__ dst,
                           const int* __restrict__ em_r, const int* __restrict__ em_c,
                           const float* __restrict__ em_v,
                           const int* __restrict__ vm_r, const int* __restrict__ vm_c,
                           const float* __restrict__ vm_v) {
    int i = blockIdx.x * 256 + threadIdx.x;
    if (i < NNZ_INC) {
        int s = src[i], e = dst[i];
        int p0 = atomicAdd(g_eCur + e, 1);
        g_eIdx[p0] = s;
        int p1 = atomicAdd(g_vCur + s, 1);
        g_vIdx[p1] = e;
        int p3 = atomicAdd(g_vmCur + vm_r[i], 1);
        g_vmCol[p3] = vm_c[i];
        g_vmVal[p3] = vm_v[i];
    }
    if (i < NNZ_E) {
        int p2 = atomicAdd(g_emCur + em_r[i], 1);
        g_emCol[p2] = em_c[i];
        g_emVal[p2] = em_v[i];
    }
}

// ---------------- gather pass: Tv[e] = sum w*vfeat[s]; S1, cnt ----------------
__global__ void edge_pass1(const float* __restrict__ vfeat, const float* __restrict__ invDV) {
    int e = (blockIdx.x * blockDim.x + threadIdx.x) >> 5;
    if (e >= NE) return;
    int lane = threadIdx.x & 31;
    int b = g_ePtr[e], t = g_ePtr[e + 1];
    float4 acc = make_float4(0.f, 0.f, 0.f, 0.f);
    float ssum = 0.f;
    int j = b;
    for (; j + 1 < t; j += 2) {
        int s0 = g_eIdx[j], s1 = g_eIdx[j + 1];
        float w0 = __ldg(invDV + s0), w1 = __ldg(invDV + s1);
        float4 v0 = __ldg(reinterpret_cast<const float4*>(vfeat + (size_t)s0 * D) + lane);
        float4 v1 = __ldg(reinterpret_cast<const float4*>(vfeat + (size_t)s1 * D) + lane);
        acc.x += w0 * v0.x + w1 * v1.x;
        acc.y += w0 * v0.y + w1 * v1.y;
        acc.z += w0 * v0.z + w1 * v1.z;
        acc.w += w0 * v0.w + w1 * v1.w;
        ssum += w0 + w1;
    }
    if (j < t) {
        int s0 = g_eIdx[j];
        float w0 = __ldg(invDV + s0);
        float4 v0 = __ldg(reinterpret_cast<const float4*>(vfeat + (size_t)s0 * D) + lane);
        acc.x += w0 * v0.x; acc.y += w0 * v0.y; acc.z += w0 * v0.z; acc.w += w0 * v0.w;
        ssum += w0;
    }
    reinterpret_cast<float4*>(g_Tv + (size_t)e * D)[lane] = acc;
    if (lane == 0) { g_S1[e] = ssum; g_cnt[e] = (float)(t - b); }
}

// ---------------- gather body: Y[node] = sum X[edge] over node's incidences -------
__device__ __forceinline__ void node_gather_body(const float* __restrict__ X,
                                                 float* __restrict__ Y) {
    int s = (blockIdx.x * blockDim.x + threadIdx.x) >> 5;
    if (s >= NN) return;
    int lane = threadIdx.x & 31;
    int b = g_vPtr[s], t = g_vPtr[s + 1];
    float4 acc = make_float4(0.f, 0.f, 0.f, 0.f);
    int j = b;
    for (; j + 1 < t; j += 2) {
        int e0 = g_vIdx[j], e1 = g_vIdx[j + 1];
        float4 v0 = __ldg(reinterpret_cast<const float4*>(X + (size_t)e0 * D) + lane);
        float4 v1 = __ldg(reinterpret_cast<const float4*>(X + (size_t)e1 * D) + lane);
        acc.x += v0.x + v1.x; acc.y += v0.y + v1.y;
        acc.z += v0.z + v1.z; acc.w += v0.w + v1.w;
    }
    if (j < t) {
        int e0 = g_vIdx[j];
        float4 v0 = __ldg(reinterpret_cast<const float4*>(X + (size_t)e0 * D) + lane);
        acc.x += v0.x; acc.y += v0.y; acc.z += v0.z; acc.w += v0.w;
    }
    reinterpret_cast<float4*>(Y + (size_t)s * D)[lane] = acc;
}

// __device__ globals bound from device code only (R8 host shadow-address bug)
__global__ void node_gather_vf2(const float* __restrict__ efeat) {
    node_gather_body(efeat, g_vf2);
}
__global__ void node_gather_vf() {
    node_gather_body(g_ef1, g_vf);
}

// ---------------- gather pass 3: T2[e]=sum vout[s]; ef2[e]=sum vf2m[s] ----------
__global__ void edge_pass3(const float* __restrict__ vout) {
    int e = (blockIdx.x * blockDim.x + threadIdx.x) >> 5;
    if (e >= NE) return;
    int lane = threadIdx.x & 31;
    int b = g_ePtr[e], t = g_ePtr[e + 1];
    float4 a1 = make_float4(0.f, 0.f, 0.f, 0.f);
    float4 a2 = make_float4(0.f, 0.f, 0.f, 0.f);
    int j = b;
    for (; j + 1 < t; j += 2) {
        int s0 = g_eIdx[j], s1 = g_eIdx[j + 1];
        float4 u0 = __ldg(reinterpret_cast<const float4*>(vout + (size_t)s0 * D) + lane);
        float4 w0 = __ldg(reinterpret_cast<const float4*>(g_vf2m + (size_t)s0 * D) + lane);
        float4 u1 = __ldg(reinterpret_cast<const float4*>(vout + (size_t)s1 * D) + lane);
        float4 w1 = __ldg(reinterpret_cast<const float4*>(g_vf2m + (size_t)s1 * D) + lane);
        a1.x += u0.x + u1.x; a1.y += u0.y + u1.y; a1.z += u0.z + u1.z; a1.w += u0.w + u1.w;
        a2.x += w0.x + w1.x; a2.y += w0.y + w1.y; a2.z += w0.z + w1.z; a2.w += w0.w + w1.w;
    }
    if (j < t) {
        int s0 = g_eIdx[j];
        float4 u0 = __ldg(reinterpret_cast<const float4*>(vout + (size_t)s0 * D) + lane);
        float4 w0 = __ldg(reinterpret_cast<const float4*>(g_vf2m + (size_t)s0 * D) + lane);
        a1.x += u0.x; a1.y += u0.y; a1.z += u0.z; a1.w += u0.w;
        a2.x += w0.x; a2.y += w0.y; a2.z += w0.z; a2.w += w0.w;
    }
    reinterpret_cast<float4*>(g_T2 + (size_t)e * D)[lane] = a1;
    reinterpret_cast<float4*>(g_ef2 + (size_t)e * D)[lane] = a2;
}

// ---------------- CSR SpMM gather: Y[r] = seed(r) + sum val*X[col] ----------------
template <bool SEED>
__device__ __forceinline__ void spmm_gather_body(const int* __restrict__ ptr,
                                                 const int* __restrict__ col,
                                                 const float* __restrict__ val,
                                                 const float* __restrict__ X,
                                                 const float* __restrict__ seed,
                                                 float* __restrict__ Y, int nrows) {
    int r = (blockIdx.x * blockDim.x + threadIdx.x) >> 5;
    if (r >= nrows) return;
    int lane = threadIdx.x & 31;
    int b = ptr[r], t = ptr[r + 1];
    float4 acc;
    if (SEED) acc = __ldg(reinterpret_cast<const float4*>(seed + (size_t)r * D) + lane);
    else      acc = make_float4(0.f, 0.f, 0.f, 0.f);
    int j = b;
    for (; j + 1 < t; j += 2) {
        int c0 = col[j], c1 = col[j + 1];
        float v0 = val[j], v1 = val[j + 1];
        float4 x0 = __ldg(reinterpret_cast<const float4*>(X + (size_t)c0 * D) + lane);
        float4 x1 = __ldg(reinterpret_cast<const float4*>(X + (size_t)c1 * D) + lane);
        acc.x += v0 * x0.x + v1 * x1.x;
        acc.y += v0 * x0.y + v1 * x1.y;
        acc.z += v0 * x0.z + v1 * x1.z;
        acc.w += v0 * x0.w + v1 * x1.w;
    }
    if (j < t) {
        int c0 = col[j];
        float v0 = val[j];
        float4 x0 = __ldg(reinterpret_cast<const float4*>(X + (size_t)c0 * D) + lane);
        acc.x += v0 * x0.x; acc.y += v0 * x0.y; acc.z += v0 * x0.z; acc.w += v0 * x0.w;
    }
    reinterpret_cast<float4*>(Y + (size_t)r * D)[lane] = acc;
}

__global__ void spmm_e_gather(const float* __restrict__ efeat) {
    spmm_gather_body<true>(g_emPtr, g_emCol, g_emVal, g_A, efeat, g_ef1, NE);
}
__global__ void spmm_v_gather() {
    spmm_gather_body<false>(g_vmPtr, g_vmCol, g_vmVal, g_vf2, nullptr, g_vf2m, NN);
}

// ---------------- GEMM: Y = X[rows,128] @ W.T (+ epilogue) ----------------
// MODE 0: plain   MODE 1: Y=acc+(P1+bias)*sc1   MODE 2: relu
// MODE 3: Y = addm + sc2*(acc + sc1*(P1+bias))
// ws row stride must be a multiple of 4 floats (LDS.128 alignment).
template <int MODE>
__device__ __forceinline__ void gemm_body(const float* __restrict__ X, const float* __restrict__ W,
                                          int ldw, int koff, float* __restrict__ Y, int rows,
                                          const float* __restrict__ P1, const float* __restrict__ sc1,
                                          const float* __restrict__ sc2, const float* __restrict__ bias,
                                          const float* __restrict__ addm) {
    __shared__ float xs[32][128];
    __shared__ __align__(16) float ws[32][132];
    int r0 = blockIdx.x * 32;
    int tid = threadIdx.x;

    for (int idx = tid; idx < 32 * 128; idx += 256) {
        int r = idx >> 7, k = idx & 127;
        int rr = r0 + r;
        xs[r][k] = (rr < rows) ? X[(size_t)rr * 128 + k] : 0.f;
    }

    int lane = tid & 31;
    int rloc = (tid >> 5) * 4;
    int o4 = lane * 4;
    float acc[4][4];
#pragma unroll
    for (int i = 0; i < 4; i++)
#pragma unroll
        for (int j = 0; j < 4; j++) acc[i][j] = 0.f;

    for (int kt = 0; kt < 128; kt += 32) {
        __syncthreads();
        for (int idx = tid; idx < 32 * 128; idx += 256) {
            int o = idx >> 5, kk = idx & 31;
            ws[kk][o] = W[(size_t)o * ldw + koff + kt + kk];
        }
        __syncthreads();
#pragma unroll
        for (int kk = 0; kk < 32; kk++) {
            float4 wv = *reinterpret_cast<const float4*>(&ws[kk][o4]);
#pragma unroll
            for (int i = 0; i < 4; i++) {
                float xv = xs[rloc + i][kt + kk];
                acc[i][0] += xv * wv.x;
                acc[i][1] += xv * wv.y;
                acc[i][2] += xv * wv.z;
                acc[i][3] += xv * wv.w;
            }
        }
    }

#pragma unroll
    for (int i = 0; i < 4; i++) {
        int rr = r0 + rloc + i;
        if (rr >= rows) continue;
        float4 res = make_float4(acc[i][0], acc[i][1], acc[i][2], acc[i][3]);
        if (MODE == 1) {
            float s = sc1[rr];
            float4 q = *reinterpret_cast<const float4*>(P1 + (size_t)rr * 128 + o4);
            float4 b = *reinterpret_cast<const float4*>(bias + o4);
            res.x += (q.x + b.x) * s;
            res.y += (q.y + b.y) * s;
            res.z += (q.z + b.z) * s;
            res.w += (q.w + b.w) * s;
        } else if (MODE == 2) {
            res.x = fmaxf(res.x, 0.f); res.y = fmaxf(res.y, 0.f);
            res.z = fmaxf(res.z, 0.f); res.w = fmaxf(res.w, 0.f);
        } else if (MODE == 3) {
            float c = sc1[rr];
            float id = sc2[rr];
            float4 q = *reinterpret_cast<const float4*>(P1 + (size_t)rr * 128 + o4);
            float4 b = *reinterpret_cast<const float4*>(bias + o4);
            float4 a = *reinterpret_cast<const float4*>(addm + (size_t)rr * 128 + o4);
            res.x = a.x + id * (res.x + c * (q.x + b.x));
            res.y = a.y + id * (res.y + c * (q.y + b.y));
            res.z = a.z + id * (res.z + c * (q.z + b.z));
            res.w = a.w + id * (res.w + c * (q.w + b.w));
        }
        *reinterpret_cast<float4*>(Y + (size_t)rr * 128 + o4) = res;
    }
}

// ---- fused Q/Q2 GEMM: shares the xs tile across both weight matrices ----
__global__ void gemm_QQ2_kernel(const float* __restrict__ efeat,
                                const float* __restrict__ p1W,
                                const float* __restrict__ p2W) {
    __shared__ float xs[32][128];
    __shared__ __align__(16) float ws[32][132];
    int r0 = blockIdx.x * 32;
    int tid = threadIdx.x;

    for (int idx = tid; idx < 32 * 128; idx += 256) {
        int r = idx >> 7, k = idx & 127;
        int rr = r0 + r;
        xs[r][k] = (rr < NE) ? efeat[(size_t)rr * 128 + k] : 0.f;
    }

    int lane = tid & 31;
    int rloc = (tid >> 5) * 4;
    int o4 = lane * 4;

#pragma unroll
    for (int w = 0; w < 2; w++) {
        const float* W = w ? p2W : p1W;
        float* Y = w ? g_Q2 : g_Q;
        float acc[4][4];
#pragma unroll
        for (int i = 0; i < 4; i++)
#pragma unroll
            for (int j = 0; j < 4; j++) acc[i][j] = 0.f;

        for (int kt = 0; kt < 128; kt += 32) {
            __syncthreads();
            for (int idx = tid; idx < 32 * 128; idx += 256) {
                int o = idx >> 5, kk = idx & 31;
                ws[kk][o] = W[(size_t)o * 256 + 128 + kt + kk];
            }
            __syncthreads();
#pragma unroll
            for (int kk = 0; kk < 32; kk++) {
                float4 wv = *reinterpret_cast<const float4*>(&ws[kk][o4]);
#pragma unroll
                for (int i = 0; i < 4; i++) {
                    float xv = xs[rloc + i][kt + kk];
                    acc[i][0] += xv * wv.x;
                    acc[i][1] += xv * wv.y;
                    acc[i][2] += xv * wv.z;
                    acc[i][3] += xv * wv.w;
                }
            }
        }
#pragma unroll
        for (int i = 0; i < 4; i++) {
            int rr = r0 + rloc + i;
            if (rr < NE)
                *reinterpret_cast<float4*>(Y + (size_t)rr * 128 + o4) =
                    make_float4(acc[i][0], acc[i][1], acc[i][2], acc[i][3]);
        }
    }
}

__global__ void gemm_A_kernel(const float* p1W, const float* p1b) {
    gemm_body<1>(g_Tv, p1W, 256, 0, g_A, NE, g_Q, g_S1, nullptr, p1b, nullptr);
}
__global__ void gemm_vout_kernel(const float* Wv, float* vout) {
    gemm_body<2>(g_vf, Wv, 128, 0, vout, NN, nullptr, nullptr, nullptr, nullptr, nullptr);
}
__global__ void gemm_B_kernel(const float* p2W, const float* p2b, const float* invDE) {
    gemm_body<3>(g_T2, p2W, 256, 0, g_M, NE, g_Q2, g_cnt, invDE, p2b, g_ef2);
}
__global__ void gemm_eout_kernel(const float* We, float* eout) {
    gemm_body<2>(g_M, We, 128, 0, eout, NE, nullptr, nullptr, nullptr, nullptr, nullptr);
}

// ---------------- launcher (two-stream fork/join, graph-capturable) ----------------
extern "C" void kernel_launch(void* const* d_in, const int* in_sizes, int n_in,
                              void* d_out, int out_size) {
    const float* vfeat  = (const float*)d_in[0];
    const float* efeat  = (const float*)d_in[1];
    const float* invDV  = (const float*)d_in[2];
    const float* invDE  = (const float*)d_in[3];
    const int*   inc_src = (const int*)d_in[4];
    const int*   inc_dst = (const int*)d_in[5];
    const int*   em_r   = (const int*)d_in[6];
    const int*   em_c   = (const int*)d_in[7];
    const float* em_v   = (const float*)d_in[8];
    const int*   vm_r   = (const int*)d_in[9];
    const int*   vm_c   = (const int*)d_in[10];
    const float* vm_v   = (const float*)d_in[11];
    const float* Wv     = (const float*)d_in[12];
    const float* We     = (const float*)d_in[13];
    const float* p1W    = (const float*)d_in[14];
    const float* p1b    = (const float*)d_in[15];
    const float* p2W    = (const float*)d_in[16];
    const float* p2b    = (const float*)d_in[17];

    float* out  = (float*)d_out;
    float* vout = out;                       // [NN, 128]
    float* eout = out + (size_t)NN * D;      // [NE, 128]

    static cudaStream_t s1 = nullptr;
    static cudaEvent_t evFork = nullptr, evBuild = nullptr, evQ = nullptr, ev2 = nullptr;
    if (s1 == nullptr) {
        cudaStreamCreateWithFlags(&s1, cudaStreamNonBlocking);
        cudaEventCreateWithFlags(&evFork, cudaEventDisableTiming);
        cudaEventCreateWithFlags(&evBuild, cudaEventDisableTiming);
        cudaEventCreateWithFlags(&evQ, cudaEventDisableTiming);
        cudaEventCreateWithFlags(&ev2, cudaEventDisableTiming);
    }

    const int TB = 256;
    int grid_z    = (NN + TB - 1) / TB;
    int grid_nnz  = (NNZ_INC + TB - 1) / TB;
    int grid_eW   = (NE * 32 + TB - 1) / TB;         // warp per edge
    int grid_nW   = (NN * 32 + TB - 1) / TB;         // warp per node
    int grid_gE   = (NE + 31) / 32;
    int grid_gN   = (NN + 31) / 32;

    // fork: s1 runs QQ2 concurrent with the CSR build on s0
    cudaEventRecord(evFork, 0);
    cudaStreamWaitEvent(s1, evFork, 0);
    gemm_QQ2_kernel<<<grid_gE, TB, 0, s1>>>(efeat, p1W, p2W);
    cudaEventRecord(evQ, s1);

    // --- CSR build (s0): zero -> hist -> 3-phase scan -> bin ---
    zero_counters<<<grid_z, TB>>>();
    hist_kernel<<<grid_nnz, TB>>>(inc_src, inc_dst, em_r, vm_r);
    scan_partial<<<NBLK, TB>>>();
    scan_offsets<<<1, 512>>>();
    scan_final<<<NBLK, TB>>>();
    bin_kernel<<<grid_nnz, TB>>>(inc_src, inc_dst, em_r, em_c, em_v, vm_r, vm_c, vm_v);
    cudaEventRecord(evBuild, 0);

    // --- s1: vf2 gather + spmm_v (co-runs with s0's edge_pass1 / gemm_A chain) ---
    cudaStreamWaitEvent(s1, evBuild, 0);
    node_gather_vf2<<<grid_nW, TB, 0, s1>>>(efeat);            // vf2
    spmm_v_gather<<<grid_nW, TB, 0, s1>>>();                   // vf2m = vmat@vf2
    cudaEventRecord(ev2, s1);

    // --- s0: main chain ---
    edge_pass1<<<grid_eW, TB>>>(vfeat, invDV);                 // Tv, S1, cnt
    cudaStreamWaitEvent(0, evQ, 0);                            // gemm_A reads g_Q
    gemm_A_kernel<<<grid_gE, TB>>>(p1W, p1b);                  // A
    spmm_e_gather<<<grid_eW, TB>>>(efeat);                     // ef1 = efeat + emat@A
    node_gather_vf<<<grid_nW, TB>>>();                         // vf
    gemm_vout_kernel<<<grid_gN, TB>>>(Wv, vout);               // vout = relu(vf@Wv.T)
    cudaStreamWaitEvent(0, ev2, 0);                            // join s1 (vf2m)
    edge_pass3<<<grid_eW, TB>>>(vout);                         // T2, ef2
    gemm_B_kernel<<<grid_gE, TB>>>(p2W, p2b, invDE);           // M (needs Q2: s1-ordered)
    gemm_eout_kernel<<<grid_gE, TB>>>(We, eout);               // eout
}